// round 2
// baseline (speedup 1.0000x reference)
#include <cuda_runtime.h>
#include <cstdint>
#include <math.h>

// ---------------- problem constants ----------------
#define BDIM 256
#define DIN 2048
#define HID 2048
#define DCTX 1024
#define NSEG 10
#define NR (HID * NSEG) /* 20480 */
#define OUTD 100
#define KWIN 102

// ---------------- scratch (no allocations allowed) ----------------
__device__ float g_d[BDIM * NR];    // dendrite activations (21 MB), reused per layer
__device__ float g_y[BDIM * HID];   // ff pre-activation / gated
__device__ float g_h1[BDIM * HID];  // layer-1 k-winners output
__device__ float g_h2[BDIM * HID];  // layer-2 k-winners output

// ---------------- f32x2 helpers (sm_103a packed fp32) ----------------
__device__ __forceinline__ unsigned long long splat2(float v) {
    unsigned long long r;
    asm("mov.b64 %0, {%1, %1};" : "=l"(r) : "f"(v));
    return r;
}
__device__ __forceinline__ void fma2(unsigned long long& c, unsigned long long a,
                                     unsigned long long b) {
    asm("fma.rn.f32x2 %0, %1, %2, %0;" : "+l"(c) : "l"(a), "l"(b));
}

// =====================================================================
// Big masked GEMM: C[m,n] = sum_k A[m,k] * W[n,k] * Msk[n,k]
// Tile 128x128, BK=8, 256 threads, 8x8 micro-tile with packed f32x2 FMA.
// Requires M%128==0, N%128==0, K%8==0 (true for all uses here).
// =====================================================================
__global__ __launch_bounds__(256, 2)
void gemm_masked_128(const float* __restrict__ A, const float* __restrict__ W,
                     const float* __restrict__ Msk, float* __restrict__ C,
                     int Kdim, int Ndim) {
    __shared__ alignas(16) float As[8][128];
    __shared__ alignas(16) float Bs[8][128];
    const int tid = threadIdx.x;
    const int m0 = blockIdx.y * 128;
    const int n0 = blockIdx.x * 128;
    const int lr = tid >> 1;        // 0..127 tile row to load
    const int lk = (tid & 1) * 4;   // 0 or 4 (k sub-chunk)
    const float* Ap = A + (size_t)(m0 + lr) * Kdim + lk;
    const float* Wp = W + (size_t)(n0 + lr) * Kdim + lk;
    const float* Mp = Msk + (size_t)(n0 + lr) * Kdim + lk;
    const int tx = tid & 15;
    const int ty = tid >> 4;

    unsigned long long acc[8][4];
#pragma unroll
    for (int i = 0; i < 8; ++i)
#pragma unroll
        for (int j = 0; j < 4; ++j) acc[i][j] = 0ull;

    float4 pa = *(const float4*)Ap;
    float4 pw = *(const float4*)Wp;
    float4 pm = *(const float4*)Mp;
    const int nk = Kdim >> 3;
    for (int kt = 0; kt < nk; ++kt) {
        As[lk + 0][lr] = pa.x;
        As[lk + 1][lr] = pa.y;
        As[lk + 2][lr] = pa.z;
        As[lk + 3][lr] = pa.w;
        Bs[lk + 0][lr] = pw.x * pm.x;
        Bs[lk + 1][lr] = pw.y * pm.y;
        Bs[lk + 2][lr] = pw.z * pm.z;
        Bs[lk + 3][lr] = pw.w * pm.w;
        __syncthreads();
        if (kt + 1 < nk) {  // register prefetch of next k-chunk
            Ap += 8; Wp += 8; Mp += 8;
            pa = *(const float4*)Ap;
            pw = *(const float4*)Wp;
            pm = *(const float4*)Mp;
        }
#pragma unroll
        for (int kk = 0; kk < 8; ++kk) {
            float4 a0 = *(const float4*)&As[kk][ty * 8];
            float4 a1 = *(const float4*)&As[kk][ty * 8 + 4];
            const unsigned long long* bp =
                reinterpret_cast<const unsigned long long*>(&Bs[kk][tx * 8]);
            unsigned long long bv0 = bp[0], bv1 = bp[1], bv2 = bp[2], bv3 = bp[3];
            unsigned long long av[8];
            av[0] = splat2(a0.x); av[1] = splat2(a0.y);
            av[2] = splat2(a0.z); av[3] = splat2(a0.w);
            av[4] = splat2(a1.x); av[5] = splat2(a1.y);
            av[6] = splat2(a1.z); av[7] = splat2(a1.w);
#pragma unroll
            for (int i = 0; i < 8; ++i) {
                fma2(acc[i][0], av[i], bv0);
                fma2(acc[i][1], av[i], bv1);
                fma2(acc[i][2], av[i], bv2);
                fma2(acc[i][3], av[i], bv3);
            }
        }
        __syncthreads();
    }
#pragma unroll
    for (int i = 0; i < 8; ++i) {
        float* crow = C + (size_t)(m0 + ty * 8 + i) * Ndim + n0 + tx * 8;
        unsigned long long* c64 = reinterpret_cast<unsigned long long*>(crow);
        c64[0] = acc[i][0];
        c64[1] = acc[i][1];
        c64[2] = acc[i][2];
        c64[3] = acc[i][3];
    }
}

// =====================================================================
// Smaller masked GEMM with bias (for FF projections): tile 64x64, BK=16.
// Grid has 128 blocks for N=2048,M=256 -> keeps the chip occupied.
// =====================================================================
__global__ __launch_bounds__(256)
void gemm_masked_64(const float* __restrict__ A, const float* __restrict__ W,
                    const float* __restrict__ Msk, const float* __restrict__ bias,
                    float* __restrict__ C, int Kdim, int Ndim) {
    __shared__ alignas(16) float As[16][64];
    __shared__ alignas(16) float Bs[16][64];
    const int tid = threadIdx.x;
    const int m0 = blockIdx.y * 64;
    const int n0 = blockIdx.x * 64;
    const int lr = tid >> 2;        // 0..63
    const int lk = (tid & 3) * 4;   // 0,4,8,12
    const float* Ap = A + (size_t)(m0 + lr) * Kdim + lk;
    const float* Wp = W + (size_t)(n0 + lr) * Kdim + lk;
    const float* Mp = Msk + (size_t)(n0 + lr) * Kdim + lk;
    const int tx = tid & 15;
    const int ty = tid >> 4;

    float acc[4][4];
#pragma unroll
    for (int i = 0; i < 4; ++i)
#pragma unroll
        for (int j = 0; j < 4; ++j) acc[i][j] = 0.f;

    float4 pa = *(const float4*)Ap;
    float4 pw = *(const float4*)Wp;
    float4 pm = *(const float4*)Mp;
    const int nk = Kdim >> 4;
    for (int kt = 0; kt < nk; ++kt) {
        As[lk + 0][lr] = pa.x; As[lk + 1][lr] = pa.y;
        As[lk + 2][lr] = pa.z; As[lk + 3][lr] = pa.w;
        Bs[lk + 0][lr] = pw.x * pm.x; Bs[lk + 1][lr] = pw.y * pm.y;
        Bs[lk + 2][lr] = pw.z * pm.z; Bs[lk + 3][lr] = pw.w * pm.w;
        __syncthreads();
        if (kt + 1 < nk) {
            Ap += 16; Wp += 16; Mp += 16;
            pa = *(const float4*)Ap;
            pw = *(const float4*)Wp;
            pm = *(const float4*)Mp;
        }
#pragma unroll
        for (int kk = 0; kk < 16; ++kk) {
            float4 a = *(const float4*)&As[kk][ty * 4];
            float4 b = *(const float4*)&Bs[kk][tx * 4];
            acc[0][0] += a.x * b.x; acc[0][1] += a.x * b.y;
            acc[0][2] += a.x * b.z; acc[0][3] += a.x * b.w;
            acc[1][0] += a.y * b.x; acc[1][1] += a.y * b.y;
            acc[1][2] += a.y * b.z; acc[1][3] += a.y * b.w;
            acc[2][0] += a.z * b.x; acc[2][1] += a.z * b.y;
            acc[2][2] += a.z * b.z; acc[2][3] += a.z * b.w;
            acc[3][0] += a.w * b.x; acc[3][1] += a.w * b.y;
            acc[3][2] += a.w * b.z; acc[3][3] += a.w * b.w;
        }
        __syncthreads();
    }
#pragma unroll
    for (int i = 0; i < 4; ++i) {
        const int m = m0 + ty * 4 + i;
#pragma unroll
        for (int j = 0; j < 4; ++j) {
            const int n = n0 + tx * 4 + j;
            C[(size_t)m * Ndim + n] = acc[i][j] + bias[n];
        }
    }
}

// =====================================================================
// Dendritic gating: y[b,u] *= sigmoid(d[b,u,argmax_s |d[b,u,s]|])
// First-occurrence argmax (strict >) to match jnp.argmax semantics.
// =====================================================================
__global__ void gate_kernel(float* __restrict__ y, const float* __restrict__ d) {
    const int idx = blockIdx.x * blockDim.x + threadIdx.x;  // b*HID + u
    const int b = idx >> 11;   // /2048
    const int u = idx & 2047;
    const float* dp = d + (size_t)b * NR + u * NSEG;
    float best = dp[0];
    float besta = fabsf(best);
#pragma unroll
    for (int s = 1; s < NSEG; ++s) {
        float v = dp[s];
        float a = fabsf(v);
        if (a > besta) { besta = a; best = v; }
    }
    const float g = 1.0f / (1.0f + expf(-best));
    y[idx] *= g;
}

// =====================================================================
// k-winners: exact top-KWIN per row via 4-pass radix select on sortable keys.
// One block per row (256 rows), 256 threads.
// =====================================================================
__global__ void kwinners_kernel(const float* __restrict__ yg, float* __restrict__ out) {
    __shared__ unsigned keys[HID];
    __shared__ int hist[256];
    __shared__ int s_digit;
    __shared__ int s_kneed;
    const int b = blockIdx.x;
    const int tid = threadIdx.x;
    const float* row = yg + (size_t)b * HID;

    for (int i = tid; i < HID; i += 256) {
        unsigned u = __float_as_uint(row[i]);
        // monotonic float->uint map (ascending)
        u = (u & 0x80000000u) ? ~u : (u | 0x80000000u);
        keys[i] = u;
    }
    if (tid == 0) s_kneed = KWIN;

    unsigned prefix = 0, pmask = 0;
    for (int pass = 0; pass < 4; ++pass) {
        const int shift = 24 - 8 * pass;
        hist[tid] = 0;
        __syncthreads();
        for (int i = tid; i < HID; i += 256) {
            unsigned u = keys[i];
            if ((u & pmask) == prefix) atomicAdd(&hist[(u >> shift) & 255], 1);
        }
        __syncthreads();
        if (tid == 0) {
            int need = s_kneed, c = 0, dg = 0;
            for (int bin = 255; bin >= 0; --bin) {
                if (c + hist[bin] >= need) { dg = bin; s_kneed = need - c; break; }
                c += hist[bin];
            }
            s_digit = dg;
        }
        __syncthreads();
        prefix |= ((unsigned)s_digit) << shift;
        pmask |= 0xFFu << shift;
    }
    const unsigned thresh = prefix;  // key of the KWIN-th largest
    for (int i = tid; i < HID; i += 256) {
        out[(size_t)b * HID + i] = (keys[i] >= thresh) ? row[i] : 0.0f;
    }
}

// =====================================================================
// EiDense head: out[b,o] = sum_u h[b,u]*Wex[o,u] - (sum_u h[b,u]*Wix[u])*Wei[o] + b_out[o]
// 4 batch rows per block, 8 warps, lane-strided reductions.
// =====================================================================
__global__ __launch_bounds__(256)
void head_kernel(const float* __restrict__ h, const float* __restrict__ Wex,
                 const float* __restrict__ Wix, const float* __restrict__ Wei,
                 const float* __restrict__ bo, float* __restrict__ out) {
    __shared__ alignas(16) float sh[4][HID];
    __shared__ float st[4];
    const int b0 = blockIdx.x * 4;
    const int tid = threadIdx.x;
    for (int i = tid; i < 4 * HID; i += 256) {
        (&sh[0][0])[i] = h[(size_t)b0 * HID + i];
    }
    __syncthreads();
    const int wid = tid >> 5;
    const int lane = tid & 31;
    if (wid < 4) {
        float p = 0.f;
        for (int u = lane; u < HID; u += 32) p += sh[wid][u] * Wix[u];
#pragma unroll
        for (int o = 16; o; o >>= 1) p += __shfl_xor_sync(0xffffffffu, p, o);
        if (lane == 0) st[wid] = p;
    }
    __syncthreads();
    for (int o = wid; o < OUTD; o += 8) {
        float a0 = 0.f, a1 = 0.f, a2 = 0.f, a3 = 0.f;
        const float* wrow = Wex + (size_t)o * HID;
        for (int u = lane; u < HID; u += 32) {
            const float w = wrow[u];
            a0 += sh[0][u] * w;
            a1 += sh[1][u] * w;
            a2 += sh[2][u] * w;
            a3 += sh[3][u] * w;
        }
#pragma unroll
        for (int s = 16; s; s >>= 1) {
            a0 += __shfl_xor_sync(0xffffffffu, a0, s);
            a1 += __shfl_xor_sync(0xffffffffu, a1, s);
            a2 += __shfl_xor_sync(0xffffffffu, a2, s);
            a3 += __shfl_xor_sync(0xffffffffu, a3, s);
        }
        if (lane == 0) {
            const float we = Wei[o];
            const float bb = bo[o];
            out[(size_t)(b0 + 0) * OUTD + o] = a0 - st[0] * we + bb;
            out[(size_t)(b0 + 1) * OUTD + o] = a1 - st[1] * we + bb;
            out[(size_t)(b0 + 2) * OUTD + o] = a2 - st[2] * we + bb;
            out[(size_t)(b0 + 3) * OUTD + o] = a3 - st[3] * we + bb;
        }
    }
}

// =====================================================================
// launch
// =====================================================================
extern "C" void kernel_launch(void* const* d_in, const int* in_sizes, int n_in,
                              void* d_out, int out_size) {
    const float* x      = (const float*)d_in[0];
    const float* ctx    = (const float*)d_in[1];
    const float* W1     = (const float*)d_in[2];
    const float* b1     = (const float*)d_in[3];
    const float* segW1  = (const float*)d_in[4];
    const float* maskW1 = (const float*)d_in[5];
    const float* maskS1 = (const float*)d_in[6];
    const float* W2     = (const float*)d_in[7];
    const float* b2     = (const float*)d_in[8];
    const float* segW2  = (const float*)d_in[9];
    const float* maskW2 = (const float*)d_in[10];
    const float* maskS2 = (const float*)d_in[11];
    const float* Wex    = (const float*)d_in[12];
    const float* Wix    = (const float*)d_in[13];
    const float* Wei    = (const float*)d_in[14];
    const float* bo     = (const float*)d_in[15];
    float* out = (float*)d_out;

    float *dd, *dy, *dh1, *dh2;
    cudaGetSymbolAddress((void**)&dd, g_d);
    cudaGetSymbolAddress((void**)&dy, g_y);
    cudaGetSymbolAddress((void**)&dh1, g_h1);
    cudaGetSymbolAddress((void**)&dh2, g_h2);

    const dim3 gridD(NR / 128, BDIM / 128);    // 160 x 2
    const dim3 gridY(HID / 64, BDIM / 64);     // 32 x 4
    const int gateBlocks = (BDIM * HID) / 256; // 2048

    // ---- layer 1 ----
    gemm_masked_128<<<gridD, 256>>>(ctx, segW1, maskS1, dd, DCTX, NR);
    gemm_masked_64<<<gridY, 256>>>(x, W1, maskW1, b1, dy, DIN, HID);
    gate_kernel<<<gateBlocks, 256>>>(dy, dd);
    kwinners_kernel<<<BDIM, 256>>>(dy, dh1);

    // ---- layer 2 ----
    gemm_masked_128<<<gridD, 256>>>(ctx, segW2, maskS2, dd, DCTX, NR);
    gemm_masked_64<<<gridY, 256>>>(dh1, W2, maskW2, b2, dy, HID, HID);
    gate_kernel<<<gateBlocks, 256>>>(dy, dd);
    kwinners_kernel<<<BDIM, 256>>>(dy, dh2);

    // ---- EiDense head ----
    head_kernel<<<BDIM / 4, 256>>>(dh2, Wex, Wix, Wei, bo, out);
}

// round 3
// speedup vs baseline: 1.0684x; 1.0684x over previous
#include <cuda_runtime.h>
#include <cstdint>
#include <math.h>

// ---------------- problem constants ----------------
#define BDIM 256
#define DIN 2048
#define HID 2048
#define DCTX 1024
#define NSEG 10
#define NR (HID * NSEG) /* 20480 */
#define OUTD 100
#define KWIN 102

#define DW 128   // ELL width for dendrite rows (mean nz = 51.2, 11 sigma headroom)
#define FW 192   // ELL width for FF rows (mean nz = 102.4, 9 sigma headroom)

typedef unsigned long long u64;

// ---------------- scratch (no allocations allowed) ----------------
__device__ float g_ctxT[DCTX * BDIM];   // 1 MB   context transposed [c][b]
__device__ float g_xT[DIN * BDIM];      // 2 MB   x transposed [c][b]
__device__ float g_hT[HID * BDIM];      // 2 MB   layer-1 winners transposed
__device__ float g_dT[NR * BDIM];       // 21 MB  dendrite activations [row][b]
__device__ float g_yT[HID * BDIM];      // 2 MB   ff pre-activation [n][b]
__device__ float g_h2[BDIM * HID];      // 2 MB   layer-2 winners, normal layout
__device__ u64  g_ellD[(size_t)NR * DW];   // 21 MB ELL (dendrite)
__device__ int  g_cntD[NR];
__device__ u64  g_ellF[(size_t)HID * FW];  // 3 MB  ELL (ff)
__device__ int  g_cntF[HID];

// =====================================================================
// 32x32 tiled transpose: in[R][C] -> out[C][R]
// =====================================================================
__global__ void transpose_k(const float* __restrict__ in, float* __restrict__ out,
                            int R, int C) {
    __shared__ float t[32][33];
    const int c0 = blockIdx.x * 32, r0 = blockIdx.y * 32;
    const int x = threadIdx.x, y = threadIdx.y;  // blockDim (32,8)
#pragma unroll
    for (int i = 0; i < 32; i += 8)
        t[y + i][x] = in[(size_t)(r0 + y + i) * C + c0 + x];
    __syncthreads();
#pragma unroll
    for (int i = 0; i < 32; i += 8)
        out[(size_t)(c0 + y + i) * R + r0 + x] = t[x][y + i];
}

// =====================================================================
// ELL build: per-row warp-ballot compaction of (W * Msk).
// Entry = (f32 weight bits << 32) | (col * mult)   (mult = byte stride)
// Deterministic ascending column order.
// =====================================================================
__global__ void build_ell(const float* __restrict__ W, const float* __restrict__ M,
                          u64* __restrict__ ell, int* __restrict__ cnt,
                          int K, int width, int mult, int nrows) {
    const int gw = (blockIdx.x * blockDim.x + threadIdx.x) >> 5;
    const int lane = threadIdx.x & 31;
    if (gw >= nrows) return;
    const float* wr = W + (size_t)gw * K;
    const float* mr = M + (size_t)gw * K;
    u64* er = ell + (size_t)gw * width;
    int base = 0;
    for (int c0 = 0; c0 < K; c0 += 32) {
        const float m = mr[c0 + lane];
        const float w = wr[c0 + lane];
        const unsigned bal = __ballot_sync(0xffffffffu, m != 0.0f);
        if (m != 0.0f) {
            const int pos = base + __popc(bal & ((1u << lane) - 1u));
            if (pos < width)
                er[pos] = ((u64)__float_as_uint(w) << 32) |
                          (unsigned)((c0 + lane) * mult);
        }
        base += __popc(bal);
    }
    if (lane == 0) cnt[gw] = base < width ? base : width;
}

// =====================================================================
// Dendrite spMM: dT[r][b] = sum_nz w * ctxT[c][b]
// Block stages ctxT[:, b0:b0+32] (128 KB) in smem; warp lanes = batch.
// One warp per row, rows strided by 8 within a 554-row group.
// =====================================================================
__global__ __launch_bounds__(256)
void dspmm(const float* __restrict__ ctxT, const u64* __restrict__ ell,
           const int* __restrict__ cnt, float* __restrict__ dT) {
    extern __shared__ float s[];  // DCTX * 32 floats = 128 KB
    const int b0 = blockIdx.y * 32;
    const int tid = threadIdx.x;
    for (int i = tid; i < DCTX * 8; i += 256) {
        const int c = i >> 3, q = i & 7;
        *(float4*)&s[c * 32 + q * 4] = *(const float4*)&ctxT[(size_t)c * 256 + b0 + q * 4];
    }
    __syncthreads();
    const int wid = tid >> 5, lane = tid & 31;
    const char* sb = (const char*)s + lane * 4;
    const int base = blockIdx.x * 554;
    const int rend = min(base + 554, NR);
    for (int r = base + wid; r < rend; r += 8) {
        const int n = cnt[r];
        const u64* e = ell + (size_t)r * DW;
        float acc = 0.f;
        int j = 0;
        for (; j + 4 <= n; j += 4) {
            const u64 e0 = e[j], e1 = e[j + 1], e2 = e[j + 2], e3 = e[j + 3];
            acc += __uint_as_float((unsigned)(e0 >> 32)) * *(const float*)(sb + (unsigned)e0);
            acc += __uint_as_float((unsigned)(e1 >> 32)) * *(const float*)(sb + (unsigned)e1);
            acc += __uint_as_float((unsigned)(e2 >> 32)) * *(const float*)(sb + (unsigned)e2);
            acc += __uint_as_float((unsigned)(e3 >> 32)) * *(const float*)(sb + (unsigned)e3);
        }
        for (; j < n; ++j) {
            const u64 e0 = e[j];
            acc += __uint_as_float((unsigned)(e0 >> 32)) * *(const float*)(sb + (unsigned)e0);
        }
        dT[(size_t)r * 256 + b0 + lane] = acc;
    }
}

// =====================================================================
// FF spMM: yT[r][b] = bias[r] + sum_nz w * xT[c][b]
// One block per output row, 256 threads = full batch; xT stays in L2.
// =====================================================================
__global__ __launch_bounds__(256)
void fspmm(const float* __restrict__ xT, const u64* __restrict__ ell,
           const int* __restrict__ cnt, const float* __restrict__ bias,
           float* __restrict__ yT) {
    const int r = blockIdx.x;
    const int tid = threadIdx.x;
    const char* xb = (const char*)xT + tid * 4;
    const u64* e = ell + (size_t)r * FW;
    const int n = cnt[r];
    float acc = 0.f;
    int j = 0;
    for (; j + 4 <= n; j += 4) {
        const u64 e0 = e[j], e1 = e[j + 1], e2 = e[j + 2], e3 = e[j + 3];
        acc += __uint_as_float((unsigned)(e0 >> 32)) * *(const float*)(xb + (unsigned)e0);
        acc += __uint_as_float((unsigned)(e1 >> 32)) * *(const float*)(xb + (unsigned)e1);
        acc += __uint_as_float((unsigned)(e2 >> 32)) * *(const float*)(xb + (unsigned)e2);
        acc += __uint_as_float((unsigned)(e3 >> 32)) * *(const float*)(xb + (unsigned)e3);
    }
    for (; j < n; ++j) {
        const u64 e0 = e[j];
        acc += __uint_as_float((unsigned)(e0 >> 32)) * *(const float*)(xb + (unsigned)e0);
    }
    yT[(size_t)r * 256 + tid] = acc + bias[r];
}

// =====================================================================
// Gating on transposed layouts: yT[u][b] *= sigmoid(d at argmax_s |d|)
// First-occurrence semantics (strict >) matching jnp.argmax.
// =====================================================================
__global__ void gate_k(float* __restrict__ yT, const float* __restrict__ dT) {
    const int lane = threadIdx.x & 31, w = threadIdx.x >> 5;
    const int u = blockIdx.x * 8 + w;
    const int b = blockIdx.y * 32 + lane;
    const float* dp = dT + ((size_t)u * NSEG) * 256 + b;
    float best = dp[0];
    float besta = fabsf(best);
#pragma unroll
    for (int s = 1; s < NSEG; ++s) {
        const float v = dp[(size_t)s * 256];
        const float a = fabsf(v);
        if (a > besta) { besta = a; best = v; }
    }
    const float g = 1.0f / (1.0f + __expf(-best));
    yT[(size_t)u * 256 + b] *= g;
}

// =====================================================================
// k-winners: exact top-KWIN per sample via 4-pass radix select with
// parallel suffix-scan bin selection. Values reconstructed from keys.
// mode 0 -> write transposed hT[i][b]; mode 1 -> write normal h[b][i].
// =====================================================================
__global__ __launch_bounds__(256)
void kwinners_k(const float* __restrict__ yT, float* __restrict__ outT,
                float* __restrict__ outN, int mode) {
    __shared__ unsigned keys[HID];
    __shared__ int hist[256];
    __shared__ int ssum[256];
    __shared__ int s_digit;
    __shared__ int s_need;
    const int b = blockIdx.x, tid = threadIdx.x;
    for (int i = tid; i < HID; i += 256) {
        unsigned u = __float_as_uint(yT[(size_t)i * 256 + b]);
        u = (u & 0x80000000u) ? ~u : (u | 0x80000000u);  // monotonic ascending
        keys[i] = u;
    }
    if (tid == 0) s_need = KWIN;
    __syncthreads();

    unsigned prefix = 0, pmask = 0;
    for (int pass = 0; pass < 4; ++pass) {
        const int shift = 24 - 8 * pass;
        hist[tid] = 0;
        __syncthreads();
        for (int i = tid; i < HID; i += 256) {
            const unsigned u = keys[i];
            if ((u & pmask) == prefix) atomicAdd(&hist[(u >> shift) & 255], 1);
        }
        __syncthreads();
        ssum[tid] = hist[tid];
        __syncthreads();
        for (int off = 1; off < 256; off <<= 1) {  // inclusive suffix sum
            const int t = (tid + off < 256) ? ssum[tid + off] : 0;
            __syncthreads();
            ssum[tid] += t;
            __syncthreads();
        }
        const int need = s_need;
        const int above = (tid < 255) ? ssum[tid + 1] : 0;
        __syncthreads();
        if (ssum[tid] >= need && above < need) {  // unique crossing bin
            s_digit = tid;
            s_need = need - above;
        }
        __syncthreads();
        prefix |= ((unsigned)s_digit) << shift;
        pmask |= 0xFFu << shift;
    }
    const unsigned thr = prefix;  // key of the KWIN-th largest
    for (int i = tid; i < HID; i += 256) {
        const unsigned u = keys[i];
        float val = 0.f;
        if (u >= thr) {
            const unsigned ob = (u & 0x80000000u) ? (u & 0x7FFFFFFFu) : ~u;
            val = __uint_as_float(ob);
        }
        if (mode == 0) outT[(size_t)i * 256 + b] = val;
        else           outN[(size_t)b * HID + i] = val;
    }
}

// =====================================================================
// EiDense head: out[b,o] = h.Wex[o] - (h.Wix)*Wei[o] + b_out[o]
// =====================================================================
__global__ __launch_bounds__(256)
void head_kernel(const float* __restrict__ h, const float* __restrict__ Wex,
                 const float* __restrict__ Wix, const float* __restrict__ Wei,
                 const float* __restrict__ bo, float* __restrict__ out) {
    __shared__ alignas(16) float sh[4][HID];
    __shared__ float st[4];
    const int b0 = blockIdx.x * 4;
    const int tid = threadIdx.x;
    for (int i = tid; i < 4 * HID; i += 256)
        (&sh[0][0])[i] = h[(size_t)b0 * HID + i];
    __syncthreads();
    const int wid = tid >> 5;
    const int lane = tid & 31;
    if (wid < 4) {
        float p = 0.f;
        for (int u = lane; u < HID; u += 32) p += sh[wid][u] * Wix[u];
#pragma unroll
        for (int o = 16; o; o >>= 1) p += __shfl_xor_sync(0xffffffffu, p, o);
        if (lane == 0) st[wid] = p;
    }
    __syncthreads();
    for (int o = wid; o < OUTD; o += 8) {
        float a0 = 0.f, a1 = 0.f, a2 = 0.f, a3 = 0.f;
        const float* wrow = Wex + (size_t)o * HID;
        for (int u = lane; u < HID; u += 32) {
            const float w = wrow[u];
            a0 += sh[0][u] * w;
            a1 += sh[1][u] * w;
            a2 += sh[2][u] * w;
            a3 += sh[3][u] * w;
        }
#pragma unroll
        for (int s = 16; s; s >>= 1) {
            a0 += __shfl_xor_sync(0xffffffffu, a0, s);
            a1 += __shfl_xor_sync(0xffffffffu, a1, s);
            a2 += __shfl_xor_sync(0xffffffffu, a2, s);
            a3 += __shfl_xor_sync(0xffffffffu, a3, s);
        }
        if (lane == 0) {
            const float we = Wei[o];
            const float bb = bo[o];
            out[(size_t)(b0 + 0) * OUTD + o] = a0 - st[0] * we + bb;
            out[(size_t)(b0 + 1) * OUTD + o] = a1 - st[1] * we + bb;
            out[(size_t)(b0 + 2) * OUTD + o] = a2 - st[2] * we + bb;
            out[(size_t)(b0 + 3) * OUTD + o] = a3 - st[3] * we + bb;
        }
    }
}

// =====================================================================
// launch
// =====================================================================
extern "C" void kernel_launch(void* const* d_in, const int* in_sizes, int n_in,
                              void* d_out, int out_size) {
    const float* x      = (const float*)d_in[0];
    const float* ctx    = (const float*)d_in[1];
    const float* W1     = (const float*)d_in[2];
    const float* b1     = (const float*)d_in[3];
    const float* segW1  = (const float*)d_in[4];
    const float* maskW1 = (const float*)d_in[5];
    const float* maskS1 = (const float*)d_in[6];
    const float* W2     = (const float*)d_in[7];
    const float* b2     = (const float*)d_in[8];
    const float* segW2  = (const float*)d_in[9];
    const float* maskW2 = (const float*)d_in[10];
    const float* maskS2 = (const float*)d_in[11];
    const float* Wex    = (const float*)d_in[12];
    const float* Wix    = (const float*)d_in[13];
    const float* Wei    = (const float*)d_in[14];
    const float* bo     = (const float*)d_in[15];
    float* out = (float*)d_out;

    float *ctxT, *xT, *hT, *dT, *yT, *h2;
    u64 *ellD, *ellF;
    int *cntD, *cntF;
    cudaGetSymbolAddress((void**)&ctxT, g_ctxT);
    cudaGetSymbolAddress((void**)&xT,   g_xT);
    cudaGetSymbolAddress((void**)&hT,   g_hT);
    cudaGetSymbolAddress((void**)&dT,   g_dT);
    cudaGetSymbolAddress((void**)&yT,   g_yT);
    cudaGetSymbolAddress((void**)&h2,   g_h2);
    cudaGetSymbolAddress((void**)&ellD, g_ellD);
    cudaGetSymbolAddress((void**)&ellF, g_ellF);
    cudaGetSymbolAddress((void**)&cntD, g_cntD);
    cudaGetSymbolAddress((void**)&cntF, g_cntF);

    const int dsmem = DCTX * 32 * 4;  // 128 KB
    cudaFuncSetAttribute(dspmm, cudaFuncAttributeMaxDynamicSharedMemorySize, dsmem);

    const dim3 tdim(32, 8);
    const dim3 gridDsp((NR + 553) / 554, 8);  // 37 x 8
    const dim3 gridGate(HID / 8, 8);          // 256 x 8

    // transposes
    transpose_k<<<dim3(DCTX / 32, BDIM / 32), tdim>>>(ctx, ctxT, BDIM, DCTX);
    transpose_k<<<dim3(DIN / 32, BDIM / 32), tdim>>>(x, xT, BDIM, DIN);

    // ---- layer 1 ----
    build_ell<<<(NR * 32 + 255) / 256, 256>>>(segW1, maskS1, ellD, cntD, DCTX, DW, 128, NR);
    build_ell<<<(HID * 32 + 255) / 256, 256>>>(W1, maskW1, ellF, cntF, DIN, FW, 1024, HID);
    fspmm<<<HID, 256>>>(xT, ellF, cntF, b1, yT);
    dspmm<<<gridDsp, 256, dsmem>>>(ctxT, ellD, cntD, dT);
    gate_k<<<gridGate, 256>>>(yT, dT);
    kwinners_k<<<BDIM, 256>>>(yT, hT, h2, 0);

    // ---- layer 2 ----
    build_ell<<<(NR * 32 + 255) / 256, 256>>>(segW2, maskS2, ellD, cntD, DCTX, DW, 128, NR);
    build_ell<<<(HID * 32 + 255) / 256, 256>>>(W2, maskW2, ellF, cntF, HID, FW, 1024, HID);
    fspmm<<<HID, 256>>>(hT, ellF, cntF, b2, yT);
    dspmm<<<gridDsp, 256, dsmem>>>(ctxT, ellD, cntD, dT);
    gate_k<<<gridGate, 256>>>(yT, dT);
    kwinners_k<<<BDIM, 256>>>(yT, hT, h2, 1);

    // ---- EiDense head ----
    head_kernel<<<BDIM / 4, 256>>>(h2, Wex, Wix, Wei, bo, out);
}

// round 4
// speedup vs baseline: 1.2896x; 1.2070x over previous
#include <cuda_runtime.h>
#include <cstdint>
#include <math.h>

// ---------------- problem constants ----------------
#define BDIM 256
#define DIN 2048
#define HID 2048
#define DCTX 1024
#define NSEG 10
#define NR (HID * NSEG) /* 20480 */
#define OUTD 100
#define KWIN 102

#define DW 128    // ELL row width (gmem) for dendrite rows (mean nz 51.2)
#define DWS 112   // staging cap in smem (8.7 sigma)
#define FW 192    // ELL width for FF rows (mean nz 102.4)

typedef unsigned long long u64;

// ---------------- scratch (no allocations allowed) ----------------
__device__ float g_ctxT[DCTX * BDIM];      // 1 MB  context transposed [c][b]
__device__ float g_xT[DIN * BDIM];         // 2 MB  x transposed [c][b]
__device__ float g_hT[HID * BDIM];         // 2 MB  layer-1 winners transposed
__device__ float g_yT[HID * BDIM];         // 2 MB  gated ff activation [n][b]
__device__ float g_gT[HID * BDIM];         // 2 MB  dendrite gate [u][b]
__device__ float g_h2[BDIM * HID];         // 2 MB  layer-2 winners, row-major
__device__ u64  g_ellD[(size_t)NR * DW];   // 21 MB ELL (dendrite)
__device__ int  g_cntD[NR];
__device__ u64  g_ellF[(size_t)HID * FW];  // 3 MB  ELL (ff)
__device__ int  g_cntF[HID];

// =====================================================================
// 32x32 tiled transpose: in[R][C] -> out[C][R]
// =====================================================================
__global__ void transpose_k(const float* __restrict__ in, float* __restrict__ out,
                            int R, int C) {
    __shared__ float t[32][33];
    const int c0 = blockIdx.x * 32, r0 = blockIdx.y * 32;
    const int x = threadIdx.x, y = threadIdx.y;  // blockDim (32,8)
#pragma unroll
    for (int i = 0; i < 32; i += 8)
        t[y + i][x] = in[(size_t)(r0 + y + i) * C + c0 + x];
    __syncthreads();
#pragma unroll
    for (int i = 0; i < 32; i += 8)
        out[(size_t)(c0 + y + i) * R + r0 + x] = t[x][y + i];
}

// =====================================================================
// ELL build v2: warp per row, float4 loads (4 LDG.128 in flight),
// shfl-based exclusive scan compaction. Entries in ascending column
// order: entry = (f32 bits << 32) | (col * mult).
// =====================================================================
__global__ __launch_bounds__(256)
void build_ell(const float* __restrict__ W, const float* __restrict__ M,
               u64* __restrict__ ell, int* __restrict__ cnt,
               int K, int width, int mult, int nrows) {
    const int row = (blockIdx.x * blockDim.x + threadIdx.x) >> 5;
    const int lane = threadIdx.x & 31;
    if (row >= nrows) return;
    const float4* wr = (const float4*)(W + (size_t)row * K);
    const float4* mr = (const float4*)(M + (size_t)row * K);
    u64* er = ell + (size_t)row * width;
    const int chunks = K >> 7;  // 128 floats per chunk (float4 per lane)
    int base = 0;
    float4 w = wr[lane];
    float4 m = mr[lane];
    for (int c = 0; c < chunks; ++c) {
        float4 wn, mn;
        if (c + 1 < chunks) {
            wn = wr[(c + 1) * 32 + lane];
            mn = mr[(c + 1) * 32 + lane];
        }
        const int cn = (m.x != 0.f) + (m.y != 0.f) + (m.z != 0.f) + (m.w != 0.f);
        int inc = cn;
#pragma unroll
        for (int o = 1; o < 32; o <<= 1) {
            const int t = __shfl_up_sync(0xffffffffu, inc, o);
            if (lane >= o) inc += t;
        }
        const int tot = __shfl_sync(0xffffffffu, inc, 31);
        int p = base + inc - cn;  // exclusive
        const int col0 = c * 128 + lane * 4;
        if (m.x != 0.f && p < width) er[p++] = ((u64)__float_as_uint(w.x) << 32) | (unsigned)((col0 + 0) * mult);
        if (m.y != 0.f && p < width) er[p++] = ((u64)__float_as_uint(w.y) << 32) | (unsigned)((col0 + 1) * mult);
        if (m.z != 0.f && p < width) er[p++] = ((u64)__float_as_uint(w.z) << 32) | (unsigned)((col0 + 2) * mult);
        if (m.w != 0.f && p < width) er[p++] = ((u64)__float_as_uint(w.w) << 32) | (unsigned)((col0 + 3) * mult);
        base += tot;
        w = wn; m = mn;
    }
    if (lane == 0) cnt[row] = base < width ? base : width;
}

// =====================================================================
// Fused dendrite spMM + gate.
// Warp handles one unit (10 segment rows): stages ELL entries into smem,
// accumulates 10 segment dots against a 32-batch ctx tile (128 KB smem),
// does first-occurrence abs-argmax + sigmoid, writes gT[u][b].
// grid (32, 8): x -> 64-unit group, y -> 32-batch group.
// =====================================================================
__global__ __launch_bounds__(256)
void dspmm_gate(const float* __restrict__ ctxT, const u64* __restrict__ ell,
                const int* __restrict__ cnt, float* __restrict__ gT) {
    extern __shared__ float s[];  // [DCTX*32] ctx tile, then u64 staging
    u64* sell = (u64*)&s[DCTX * 32];
    const int b0 = blockIdx.y * 32;
    const int tid = threadIdx.x;
    // stage ctxT[:, b0:b0+32] -> s[c*32 + q]
    for (int i = tid; i < DCTX * 8; i += 256) {
        const int c = i >> 3, q = i & 7;
        *(float4*)&s[c * 32 + q * 4] =
            *(const float4*)&ctxT[(size_t)c * 256 + b0 + q * 4];
    }
    __syncthreads();
    const int wid = tid >> 5, lane = tid & 31;
    const char* sb = (const char*)s + lane * 4;
    u64* ws = sell + (size_t)wid * (NSEG * DWS);

    for (int i = 0; i < 8; ++i) {
        const int u = blockIdx.x * 64 + i * 8 + wid;
        const int r0 = u * NSEG;
        int cn0 = (lane < NSEG) ? cnt[r0 + lane] : 0;
        if (cn0 > DWS) cn0 = DWS;
        // stage this unit's entries (coalesced per segment)
#pragma unroll
        for (int sg = 0; sg < NSEG; ++sg) {
            const int n = __shfl_sync(0xffffffffu, cn0, sg);
            const u64* e = ell + (size_t)(r0 + sg) * DW;
            for (int j = lane; j < n; j += 32) ws[sg * DWS + j] = e[j];
        }
        __syncwarp();
        float accs[NSEG];
#pragma unroll
        for (int sg = 0; sg < NSEG; ++sg) {
            const int n = __shfl_sync(0xffffffffu, cn0, sg);
            const u64* e = ws + sg * DWS;
            float acc = 0.f;
            int j = 0;
            for (; j + 4 <= n; j += 4) {
                const u64 e0 = e[j], e1 = e[j + 1], e2 = e[j + 2], e3 = e[j + 3];
                acc += __uint_as_float((unsigned)(e0 >> 32)) * *(const float*)(sb + (unsigned)e0);
                acc += __uint_as_float((unsigned)(e1 >> 32)) * *(const float*)(sb + (unsigned)e1);
                acc += __uint_as_float((unsigned)(e2 >> 32)) * *(const float*)(sb + (unsigned)e2);
                acc += __uint_as_float((unsigned)(e3 >> 32)) * *(const float*)(sb + (unsigned)e3);
            }
            for (; j < n; ++j) {
                const u64 e0 = e[j];
                acc += __uint_as_float((unsigned)(e0 >> 32)) * *(const float*)(sb + (unsigned)e0);
            }
            accs[sg] = acc;
        }
        __syncwarp();
        // first-occurrence abs-argmax (strict >) + sigmoid
        float best = accs[0];
        float ba = fabsf(best);
#pragma unroll
        for (int sg = 1; sg < NSEG; ++sg) {
            const float v = accs[sg];
            const float a = fabsf(v);
            if (a > ba) { ba = a; best = v; }
        }
        gT[(size_t)u * 256 + b0 + lane] = 1.0f / (1.0f + __expf(-best));
    }
}

// =====================================================================
// FF spMM with fused gate: yT[r][b] = (bias[r] + sum w*xT[c][b]) * gT[r][b]
// One block per output row; entries staged in smem; unroll 8 for L2 MLP.
// =====================================================================
__global__ __launch_bounds__(256)
void fspmm_gate(const float* __restrict__ xT, const u64* __restrict__ ell,
                const int* __restrict__ cnt, const float* __restrict__ bias,
                const float* __restrict__ gT, float* __restrict__ yT) {
    __shared__ u64 fe[FW];
    const int r = blockIdx.x;
    const int tid = threadIdx.x;
    const int n = cnt[r];
    for (int j = tid; j < n; j += 256) fe[j] = ell[(size_t)r * FW + j];
    __syncthreads();
    const char* xb = (const char*)xT + tid * 4;
    float acc = 0.f;
    int j = 0;
    for (; j + 8 <= n; j += 8) {
        float p = 0.f;
#pragma unroll
        for (int q = 0; q < 8; ++q) {
            const u64 e = fe[j + q];
            p += __uint_as_float((unsigned)(e >> 32)) * *(const float*)(xb + (unsigned)e);
        }
        acc += p;
    }
    for (; j < n; ++j) {
        const u64 e = fe[j];
        acc += __uint_as_float((unsigned)(e >> 32)) * *(const float*)(xb + (unsigned)e);
    }
    yT[(size_t)r * 256 + tid] = (acc + bias[r]) * gT[(size_t)r * 256 + tid];
}

// =====================================================================
// k-winners: exact top-KWIN per sample, 4-pass radix select with
// parallel suffix-scan bin selection; values reconstructed from keys.
// mode 0 -> transposed hT[i][b]; mode 1 -> row-major h[b][i].
// =====================================================================
__global__ __launch_bounds__(256)
void kwinners_k(const float* __restrict__ yT, float* __restrict__ outT,
                float* __restrict__ outN, int mode) {
    __shared__ unsigned keys[HID];
    __shared__ int hist[256];
    __shared__ int ssum[256];
    __shared__ int s_digit;
    __shared__ int s_need;
    const int b = blockIdx.x, tid = threadIdx.x;
    for (int i = tid; i < HID; i += 256) {
        unsigned u = __float_as_uint(yT[(size_t)i * 256 + b]);
        u = (u & 0x80000000u) ? ~u : (u | 0x80000000u);  // monotonic ascending
        keys[i] = u;
    }
    if (tid == 0) s_need = KWIN;
    __syncthreads();

    unsigned prefix = 0, pmask = 0;
    for (int pass = 0; pass < 4; ++pass) {
        const int shift = 24 - 8 * pass;
        hist[tid] = 0;
        __syncthreads();
        for (int i = tid; i < HID; i += 256) {
            const unsigned u = keys[i];
            if ((u & pmask) == prefix) atomicAdd(&hist[(u >> shift) & 255], 1);
        }
        __syncthreads();
        ssum[tid] = hist[tid];
        __syncthreads();
        for (int off = 1; off < 256; off <<= 1) {  // inclusive suffix sum
            const int t = (tid + off < 256) ? ssum[tid + off] : 0;
            __syncthreads();
            ssum[tid] += t;
            __syncthreads();
        }
        const int need = s_need;
        const int above = (tid < 255) ? ssum[tid + 1] : 0;
        __syncthreads();
        if (ssum[tid] >= need && above < need) {  // unique crossing bin
            s_digit = tid;
            s_need = need - above;
        }
        __syncthreads();
        prefix |= ((unsigned)s_digit) << shift;
        pmask |= 0xFFu << shift;
    }
    const unsigned thr = prefix;  // key of the KWIN-th largest
    for (int i = tid; i < HID; i += 256) {
        const unsigned u = keys[i];
        float val = 0.f;
        if (u >= thr) {
            const unsigned ob = (u & 0x80000000u) ? (u & 0x7FFFFFFFu) : ~u;
            val = __uint_as_float(ob);
        }
        if (mode == 0) outT[(size_t)i * 256 + b] = val;
        else           outN[(size_t)b * HID + i] = val;
    }
}

// =====================================================================
// EiDense head: out[b,o] = h.Wex[o] - (h.Wix)*Wei[o] + b_out[o]
// =====================================================================
__global__ __launch_bounds__(256)
void head_kernel(const float* __restrict__ h, const float* __restrict__ Wex,
                 const float* __restrict__ Wix, const float* __restrict__ Wei,
                 const float* __restrict__ bo, float* __restrict__ out) {
    __shared__ alignas(16) float sh[4][HID];
    __shared__ float st[4];
    const int b0 = blockIdx.x * 4;
    const int tid = threadIdx.x;
    for (int i = tid; i < 4 * HID; i += 256)
        (&sh[0][0])[i] = h[(size_t)b0 * HID + i];
    __syncthreads();
    const int wid = tid >> 5;
    const int lane = tid & 31;
    if (wid < 4) {
        float p = 0.f;
        for (int u = lane; u < HID; u += 32) p += sh[wid][u] * Wix[u];
#pragma unroll
        for (int o = 16; o; o >>= 1) p += __shfl_xor_sync(0xffffffffu, p, o);
        if (lane == 0) st[wid] = p;
    }
    __syncthreads();
    for (int o = wid; o < OUTD; o += 8) {
        float a0 = 0.f, a1 = 0.f, a2 = 0.f, a3 = 0.f;
        const float* wrow = Wex + (size_t)o * HID;
        for (int u = lane; u < HID; u += 32) {
            const float w = wrow[u];
            a0 += sh[0][u] * w;
            a1 += sh[1][u] * w;
            a2 += sh[2][u] * w;
            a3 += sh[3][u] * w;
        }
#pragma unroll
        for (int sft = 16; sft; sft >>= 1) {
            a0 += __shfl_xor_sync(0xffffffffu, a0, sft);
            a1 += __shfl_xor_sync(0xffffffffu, a1, sft);
            a2 += __shfl_xor_sync(0xffffffffu, a2, sft);
            a3 += __shfl_xor_sync(0xffffffffu, a3, sft);
        }
        if (lane == 0) {
            const float we = Wei[o];
            const float bb = bo[o];
            out[(size_t)(b0 + 0) * OUTD + o] = a0 - st[0] * we + bb;
            out[(size_t)(b0 + 1) * OUTD + o] = a1 - st[1] * we + bb;
            out[(size_t)(b0 + 2) * OUTD + o] = a2 - st[2] * we + bb;
            out[(size_t)(b0 + 3) * OUTD + o] = a3 - st[3] * we + bb;
        }
    }
}

// =====================================================================
// launch
// =====================================================================
extern "C" void kernel_launch(void* const* d_in, const int* in_sizes, int n_in,
                              void* d_out, int out_size) {
    const float* x      = (const float*)d_in[0];
    const float* ctx    = (const float*)d_in[1];
    const float* W1     = (const float*)d_in[2];
    const float* b1     = (const float*)d_in[3];
    const float* segW1  = (const float*)d_in[4];
    const float* maskW1 = (const float*)d_in[5];
    const float* maskS1 = (const float*)d_in[6];
    const float* W2     = (const float*)d_in[7];
    const float* b2     = (const float*)d_in[8];
    const float* segW2  = (const float*)d_in[9];
    const float* maskW2 = (const float*)d_in[10];
    const float* maskS2 = (const float*)d_in[11];
    const float* Wex    = (const float*)d_in[12];
    const float* Wix    = (const float*)d_in[13];
    const float* Wei    = (const float*)d_in[14];
    const float* bo     = (const float*)d_in[15];
    float* out = (float*)d_out;

    float *ctxT, *xT, *hT, *yT, *gT, *h2;
    u64 *ellD, *ellF;
    int *cntD, *cntF;
    cudaGetSymbolAddress((void**)&ctxT, g_ctxT);
    cudaGetSymbolAddress((void**)&xT,   g_xT);
    cudaGetSymbolAddress((void**)&hT,   g_hT);
    cudaGetSymbolAddress((void**)&yT,   g_yT);
    cudaGetSymbolAddress((void**)&gT,   g_gT);
    cudaGetSymbolAddress((void**)&h2,   g_h2);
    cudaGetSymbolAddress((void**)&ellD, g_ellD);
    cudaGetSymbolAddress((void**)&ellF, g_ellF);
    cudaGetSymbolAddress((void**)&cntD, g_cntD);
    cudaGetSymbolAddress((void**)&cntF, g_cntF);

    const int dsmem = DCTX * 32 * 4 + NSEG * DWS * 8 * 8;  // 128K + 70K = 198.5 KB
    static int attr_done = 0;
    cudaFuncSetAttribute(dspmm_gate, cudaFuncAttributeMaxDynamicSharedMemorySize, dsmem);
    (void)attr_done;

    const dim3 tdim(32, 8);
    const dim3 gridDsp(32, 8);  // 64 units per block x, 32 batch per block y

    // transposes
    transpose_k<<<dim3(DCTX / 32, BDIM / 32), tdim>>>(ctx, ctxT, BDIM, DCTX);
    transpose_k<<<dim3(DIN / 32, BDIM / 32), tdim>>>(x, xT, BDIM, DIN);

    // ---- layer 1 ----
    build_ell<<<NR / 8, 256>>>(segW1, maskS1, ellD, cntD, DCTX, DW, 128, NR);
    build_ell<<<HID / 8, 256>>>(W1, maskW1, ellF, cntF, DIN, FW, 1024, HID);
    dspmm_gate<<<gridDsp, 256, dsmem>>>(ctxT, ellD, cntD, gT);
    fspmm_gate<<<HID, 256>>>(xT, ellF, cntF, b1, gT, yT);
    kwinners_k<<<BDIM, 256>>>(yT, hT, h2, 0);

    // ---- layer 2 ----
    build_ell<<<NR / 8, 256>>>(segW2, maskS2, ellD, cntD, DCTX, DW, 128, NR);
    build_ell<<<HID / 8, 256>>>(W2, maskW2, ellF, cntF, HID, FW, 1024, HID);
    dspmm_gate<<<gridDsp, 256, dsmem>>>(ctxT, ellD, cntD, gT);
    fspmm_gate<<<HID, 256>>>(hT, ellF, cntF, b2, gT, yT);
    kwinners_k<<<BDIM, 256>>>(yT, hT, h2, 1);

    // ---- EiDense head ----
    head_kernel<<<BDIM / 4, 256>>>(h2, Wex, Wix, Wei, bo, out);
}

// round 6
// speedup vs baseline: 2.7876x; 2.1616x over previous
#include <cuda_runtime.h>
#include <cstdint>
#include <math.h>

// ---------------- problem constants ----------------
#define BDIM 256
#define DIN 2048
#define HID 2048
#define DCTX 1024
#define NSEG 10
#define NR (HID * NSEG) /* 20480 */
#define OUTD 100
#define KWIN 102

#define DW 128    // ELL row width for dendrite rows (mean nz 51.2)
#define FW 192    // ELL width for FF rows (mean nz 102.4)

typedef unsigned long long u64;

// ---------------- scratch (no allocations allowed) ----------------
__device__ float g_ctxT[DCTX * BDIM];       // 1 MB  context transposed [c][b]
__device__ float g_xT[DIN * BDIM];          // 2 MB  x transposed [c][b]
__device__ float g_hT[HID * BDIM];          // 2 MB  layer-1 winners transposed
__device__ float g_yT[HID * BDIM];          // 2 MB  ff pre-activation [n][b]
__device__ float g_gT1[HID * BDIM];         // 2 MB  dendrite gate layer 1 [u][b]
__device__ float g_gT2[HID * BDIM];         // 2 MB  dendrite gate layer 2 [u][b]
__device__ float g_h2[BDIM * HID];          // 2 MB  layer-2 winners, row-major
__device__ u64  g_ellD1[(size_t)NR * DW];   // 21 MB ELL (dendrite L1)
__device__ u64  g_ellD2[(size_t)NR * DW];   // 21 MB ELL (dendrite L2)
__device__ int  g_cntD1[NR];
__device__ int  g_cntD2[NR];
__device__ u64  g_ellF1[(size_t)HID * FW];  // 3 MB  ELL (ff L1)
__device__ u64  g_ellF2[(size_t)HID * FW];  // 3 MB  ELL (ff L2)
__device__ int  g_cntF1[HID];
__device__ int  g_cntF2[HID];

// =====================================================================
// warp-per-row ELL compaction: float4 loads + shfl exclusive scan.
// entry = (f32 weight bits << 32) | (col * mult), ascending column order.
// =====================================================================
__device__ __forceinline__
void build_row(const float* __restrict__ W, const float* __restrict__ M,
               u64* __restrict__ ell, int* __restrict__ cnt,
               int K, int width, int mult, int row, int lane) {
    const float4* wr = (const float4*)(W + (size_t)row * K);
    const float4* mr = (const float4*)(M + (size_t)row * K);
    u64* er = ell + (size_t)row * width;
    const int chunks = K >> 7;  // 128 floats per chunk (float4 per lane)
    int base = 0;
    float4 w = wr[lane];
    float4 m = mr[lane];
    for (int c = 0; c < chunks; ++c) {
        float4 wn, mn;
        if (c + 1 < chunks) {
            wn = wr[(c + 1) * 32 + lane];
            mn = mr[(c + 1) * 32 + lane];
        }
        const int cn = (m.x != 0.f) + (m.y != 0.f) + (m.z != 0.f) + (m.w != 0.f);
        int inc = cn;
#pragma unroll
        for (int o = 1; o < 32; o <<= 1) {
            const int t = __shfl_up_sync(0xffffffffu, inc, o);
            if (lane >= o) inc += t;
        }
        const int tot = __shfl_sync(0xffffffffu, inc, 31);
        int p = base + inc - cn;  // exclusive position
        const int col0 = c * 128 + lane * 4;
        if (m.x != 0.f && p < width) er[p++] = ((u64)__float_as_uint(w.x) << 32) | (unsigned)((col0 + 0) * mult);
        if (m.y != 0.f && p < width) er[p++] = ((u64)__float_as_uint(w.y) << 32) | (unsigned)((col0 + 1) * mult);
        if (m.z != 0.f && p < width) er[p++] = ((u64)__float_as_uint(w.z) << 32) | (unsigned)((col0 + 2) * mult);
        if (m.w != 0.f && p < width) er[p++] = ((u64)__float_as_uint(w.w) << 32) | (unsigned)((col0 + 3) * mult);
        base += tot;
        w = wn; m = mn;
    }
    if (lane == 0) cnt[row] = base < width ? base : width;
}

// =====================================================================
// K1: fused prep — all four ELL builds + both transposes in one launch.
// Block ranges (FIXED decode: /2560 and %2560, not >>11/&2047):
//   [0,2560)      build dendrite L1   (8 rows/block, 2560*8 = 20480 rows)
//   [2560,5120)   build dendrite L2
//   [5120,5376)   build FF L1         (256*8 = 2048 rows)
//   [5376,5632)   build FF L2
//   [5632,5888)   transpose ctx  (32x8)
//   [5888,6400)   transpose x    (64x8)
// =====================================================================
__global__ __launch_bounds__(256)
void prep_k(const float* __restrict__ segW1, const float* __restrict__ maskS1,
            const float* __restrict__ segW2, const float* __restrict__ maskS2,
            const float* __restrict__ W1, const float* __restrict__ maskW1,
            const float* __restrict__ W2, const float* __restrict__ maskW2,
            const float* __restrict__ ctx, const float* __restrict__ x) {
    const int bid = blockIdx.x;
    const int tid = threadIdx.x;
    const int lane = tid & 31;
    const int wid = tid >> 5;

    if (bid < 5120) {  // dendrite builds
        const int part = bid / 2560;                 // 0 or 1
        const int row = (bid % 2560) * 8 + wid;      // 0..20479
        if (part == 0) build_row(segW1, maskS1, g_ellD1, g_cntD1, DCTX, DW, 128, row, lane);
        else           build_row(segW2, maskS2, g_ellD2, g_cntD2, DCTX, DW, 128, row, lane);
        return;
    }
    if (bid < 5632) {  // FF builds
        const int part = (bid - 5120) >> 8;          // 0 or 1 (256 blocks each)
        const int row = ((bid - 5120) & 255) * 8 + wid;
        if (part == 0) build_row(W1, maskW1, g_ellF1, g_cntF1, DIN, FW, 1024, row, lane);
        else           build_row(W2, maskW2, g_ellF2, g_cntF2, HID, FW, 1024, row, lane);
        return;
    }
    // transposes: in[R=256][C] -> out[C][256]
    __shared__ float t[32][33];
    const float* in;
    float* outp;
    int C, lb;
    if (bid < 5888) { in = ctx; outp = g_ctxT; C = DCTX; lb = bid - 5632; }
    else            { in = x;   outp = g_xT;   C = DIN;  lb = bid - 5888; }
    const int nbx = C >> 5;
    const int c0 = (lb % nbx) * 32;
    const int r0 = (lb / nbx) * 32;
    const int xx = tid & 31, yy = tid >> 5;
#pragma unroll
    for (int i = 0; i < 32; i += 8)
        t[yy + i][xx] = in[(size_t)(r0 + yy + i) * C + c0 + xx];
    __syncthreads();
#pragma unroll
    for (int i = 0; i < 32; i += 8)
        outp[(size_t)(c0 + yy + i) * BDIM + r0 + xx] = t[xx][yy + i];
}

// =====================================================================
// K2: fused dendrite spMM + gate for BOTH layers.
// 1024 threads (32 warps), smem = 32-batch ctx tile (128 KB) only.
// ELL entries read as uniform LDG.64 broadcasts (L2-resident).
// grid = 256 linear: [layer(2)][by(8)][bx(16)]; block covers 128 units
// (4 per warp) x 32 batches. Writes gate = sigmoid(chosen d).
// =====================================================================
__global__ __launch_bounds__(1024, 1)
void dspmm_gate2(const float* __restrict__ ctxT) {
    extern __shared__ float s[];  // DCTX * 32 floats = 128 KB
    const int id = blockIdx.x;
    const int layer = id >> 7;
    const int bx = (id & 127) & 15;
    const int by = (id & 127) >> 4;
    const u64* __restrict__ ell = layer ? g_ellD2 : g_ellD1;
    const int* __restrict__ cnt = layer ? g_cntD2 : g_cntD1;
    float* __restrict__ gT = layer ? g_gT2 : g_gT1;

    const int b0 = by * 32;
    const int tid = threadIdx.x;
    for (int i = tid; i < DCTX * 8; i += 1024) {
        const int c = i >> 3, q = (i & 7) * 4;
        *(float4*)&s[c * 32 + q] =
            *(const float4*)&ctxT[(size_t)c * 256 + b0 + q];
    }
    __syncthreads();
    const int wid = tid >> 5, lane = tid & 31;
    const char* sb = (const char*)s + lane * 4;

#pragma unroll
    for (int i = 0; i < 4; ++i) {
        const int u = bx * 128 + wid * 4 + i;
        const int r0 = u * NSEG;
        int cn = (lane < NSEG) ? cnt[r0 + lane] : 0;
        if (cn > DW) cn = DW;
        float accs[NSEG];
#pragma unroll
        for (int sg = 0; sg < NSEG; ++sg) {
            const int n = __shfl_sync(0xffffffffu, cn, sg);
            const u64* e = ell + (size_t)(r0 + sg) * DW;
            float acc = 0.f;
            int j = 0;
            for (; j + 4 <= n; j += 4) {
                const u64 e0 = e[j], e1 = e[j + 1], e2 = e[j + 2], e3 = e[j + 3];
                acc += __uint_as_float((unsigned)(e0 >> 32)) * *(const float*)(sb + (unsigned)e0);
                acc += __uint_as_float((unsigned)(e1 >> 32)) * *(const float*)(sb + (unsigned)e1);
                acc += __uint_as_float((unsigned)(e2 >> 32)) * *(const float*)(sb + (unsigned)e2);
                acc += __uint_as_float((unsigned)(e3 >> 32)) * *(const float*)(sb + (unsigned)e3);
            }
            for (; j < n; ++j) {
                const u64 e0 = e[j];
                acc += __uint_as_float((unsigned)(e0 >> 32)) * *(const float*)(sb + (unsigned)e0);
            }
            accs[sg] = acc;
        }
        // first-occurrence abs-argmax (strict >) + sigmoid
        float best = accs[0];
        float ba = fabsf(best);
#pragma unroll
        for (int sg = 1; sg < NSEG; ++sg) {
            const float v = accs[sg];
            const float a = fabsf(v);
            if (a > ba) { ba = a; best = v; }
        }
        gT[(size_t)u * 256 + b0 + lane] = 1.0f / (1.0f + __expf(-best));
    }
}

// =====================================================================
// FF spMM: yT[r][b] = bias[r] + sum w*xT[c][b]   (gate applied later)
// One block per output row; entries staged in smem; unroll 8 for L2 MLP.
// =====================================================================
__global__ __launch_bounds__(256)
void fspmm(const float* __restrict__ xT, const u64* __restrict__ ell,
           const int* __restrict__ cnt, const float* __restrict__ bias,
           float* __restrict__ yT) {
    __shared__ u64 fe[FW];
    const int r = blockIdx.x;
    const int tid = threadIdx.x;
    const int n = cnt[r];
    for (int j = tid; j < n; j += 256) fe[j] = ell[(size_t)r * FW + j];
    __syncthreads();
    const char* xb = (const char*)xT + tid * 4;
    float acc = 0.f;
    int j = 0;
    for (; j + 8 <= n; j += 8) {
        float p = 0.f;
#pragma unroll
        for (int q = 0; q < 8; ++q) {
            const u64 e = fe[j + q];
            p += __uint_as_float((unsigned)(e >> 32)) * *(const float*)(xb + (unsigned)e);
        }
        acc += p;
    }
    for (; j < n; ++j) {
        const u64 e = fe[j];
        acc += __uint_as_float((unsigned)(e >> 32)) * *(const float*)(xb + (unsigned)e);
    }
    yT[(size_t)r * 256 + tid] = acc + bias[r];
}

// =====================================================================
// k-winners with fused gate: val = yT[i][b] * gT[i][b]; exact top-KWIN
// via 4-pass radix select; bin selection by single-warp shfl suffix scan.
// mode 0 -> transposed hT[i][b]; mode 1 -> row-major h[b][i].
// =====================================================================
__global__ __launch_bounds__(256)
void kwinners_k(const float* __restrict__ yT, const float* __restrict__ gT,
                float* __restrict__ outT, float* __restrict__ outN, int mode) {
    __shared__ unsigned keys[HID];
    __shared__ int hist[256];
    __shared__ int s_digit;
    __shared__ int s_need;
    const int b = blockIdx.x, tid = threadIdx.x;
    for (int i = tid; i < HID; i += 256) {
        const float v = yT[(size_t)i * 256 + b] * gT[(size_t)i * 256 + b];
        unsigned u = __float_as_uint(v);
        u = (u & 0x80000000u) ? ~u : (u | 0x80000000u);  // monotonic ascending
        keys[i] = u;
    }
    if (tid == 0) s_need = KWIN;
    __syncthreads();

    unsigned prefix = 0, pmask = 0;
    for (int pass = 0; pass < 4; ++pass) {
        const int shift = 24 - 8 * pass;
        hist[tid] = 0;
        __syncthreads();
        for (int i = tid; i < HID; i += 256) {
            const unsigned u = keys[i];
            if ((u & pmask) == prefix) atomicAdd(&hist[(u >> shift) & 255], 1);
        }
        __syncthreads();
        if (tid < 32) {
            const int need = s_need;
            const int base = tid * 8;
            int gs = 0;
#pragma unroll
            for (int k = 0; k < 8; ++k) gs += hist[base + k];
            int S = gs;  // inclusive suffix sum across lanes
#pragma unroll
            for (int o = 1; o < 32; o <<= 1) {
                const int t = __shfl_down_sync(0xffffffffu, S, o);
                if (tid + o < 32) S += t;
            }
            int Snext = __shfl_down_sync(0xffffffffu, S, 1);
            if (tid == 31) Snext = 0;
            if (S >= need && Snext < need) {  // unique crossing lane
                int c = Snext;
#pragma unroll
                for (int k = 7; k >= 0; --k) {
                    const int hb = hist[base + k];
                    if (c + hb >= need) { s_digit = base + k; s_need = need - c; break; }
                    c += hb;
                }
            }
        }
        __syncthreads();
        prefix |= ((unsigned)s_digit) << shift;
        pmask |= 0xFFu << shift;
    }
    const unsigned thr = prefix;  // key of the KWIN-th largest
    for (int i = tid; i < HID; i += 256) {
        const unsigned u = keys[i];
        float val = 0.f;
        if (u >= thr) {
            const unsigned ob = (u & 0x80000000u) ? (u & 0x7FFFFFFFu) : ~u;
            val = __uint_as_float(ob);
        }
        if (mode == 0) outT[(size_t)i * 256 + b] = val;
        else           outN[(size_t)b * HID + i] = val;
    }
}

// =====================================================================
// EiDense head: out[b,o] = h.Wex[o] - (h.Wix)*Wei[o] + b_out[o]
// =====================================================================
__global__ __launch_bounds__(256)
void head_kernel(const float* __restrict__ h, const float* __restrict__ Wex,
                 const float* __restrict__ Wix, const float* __restrict__ Wei,
                 const float* __restrict__ bo, float* __restrict__ out) {
    __shared__ alignas(16) float sh[4][HID];
    __shared__ float st[4];
    const int b0 = blockIdx.x * 4;
    const int tid = threadIdx.x;
    for (int i = tid; i < 4 * HID; i += 256)
        (&sh[0][0])[i] = h[(size_t)b0 * HID + i];
    __syncthreads();
    const int wid = tid >> 5;
    const int lane = tid & 31;
    if (wid < 4) {
        float p = 0.f;
        for (int u = lane; u < HID; u += 32) p += sh[wid][u] * Wix[u];
#pragma unroll
        for (int o = 16; o; o >>= 1) p += __shfl_xor_sync(0xffffffffu, p, o);
        if (lane == 0) st[wid] = p;
    }
    __syncthreads();
    for (int o = wid; o < OUTD; o += 8) {
        float a0 = 0.f, a1 = 0.f, a2 = 0.f, a3 = 0.f;
        const float* wrow = Wex + (size_t)o * HID;
        for (int u = lane; u < HID; u += 32) {
            const float w = wrow[u];
            a0 += sh[0][u] * w;
            a1 += sh[1][u] * w;
            a2 += sh[2][u] * w;
            a3 += sh[3][u] * w;
        }
#pragma unroll
        for (int sft = 16; sft; sft >>= 1) {
            a0 += __shfl_xor_sync(0xffffffffu, a0, sft);
            a1 += __shfl_xor_sync(0xffffffffu, a1, sft);
            a2 += __shfl_xor_sync(0xffffffffu, a2, sft);
            a3 += __shfl_xor_sync(0xffffffffu, a3, sft);
        }
        if (lane == 0) {
            const float we = Wei[o];
            const float bb = bo[o];
            out[(size_t)(b0 + 0) * OUTD + o] = a0 - st[0] * we + bb;
            out[(size_t)(b0 + 1) * OUTD + o] = a1 - st[1] * we + bb;
            out[(size_t)(b0 + 2) * OUTD + o] = a2 - st[2] * we + bb;
            out[(size_t)(b0 + 3) * OUTD + o] = a3 - st[3] * we + bb;
        }
    }
}

// =====================================================================
// launch
// =====================================================================
extern "C" void kernel_launch(void* const* d_in, const int* in_sizes, int n_in,
                              void* d_out, int out_size) {
    const float* x      = (const float*)d_in[0];
    const float* ctx    = (const float*)d_in[1];
    const float* W1     = (const float*)d_in[2];
    const float* b1     = (const float*)d_in[3];
    const float* segW1  = (const float*)d_in[4];
    const float* maskW1 = (const float*)d_in[5];
    const float* maskS1 = (const float*)d_in[6];
    const float* W2     = (const float*)d_in[7];
    const float* b2     = (const float*)d_in[8];
    const float* segW2  = (const float*)d_in[9];
    const float* maskW2 = (const float*)d_in[10];
    const float* maskS2 = (const float*)d_in[11];
    const float* Wex    = (const float*)d_in[12];
    const float* Wix    = (const float*)d_in[13];
    const float* Wei    = (const float*)d_in[14];
    const float* bo     = (const float*)d_in[15];
    float* out = (float*)d_out;

    float *ctxT, *xT, *hT, *yT, *gT1, *gT2, *h2;
    u64 *ellF1, *ellF2;
    int *cntF1, *cntF2;
    cudaGetSymbolAddress((void**)&ctxT,  g_ctxT);
    cudaGetSymbolAddress((void**)&xT,    g_xT);
    cudaGetSymbolAddress((void**)&hT,    g_hT);
    cudaGetSymbolAddress((void**)&yT,    g_yT);
    cudaGetSymbolAddress((void**)&gT1,   g_gT1);
    cudaGetSymbolAddress((void**)&gT2,   g_gT2);
    cudaGetSymbolAddress((void**)&h2,    g_h2);
    cudaGetSymbolAddress((void**)&ellF1, g_ellF1);
    cudaGetSymbolAddress((void**)&ellF2, g_ellF2);
    cudaGetSymbolAddress((void**)&cntF1, g_cntF1);
    cudaGetSymbolAddress((void**)&cntF2, g_cntF2);

    const int dsmem = DCTX * 32 * 4;  // 128 KB
    cudaFuncSetAttribute(dspmm_gate2, cudaFuncAttributeMaxDynamicSharedMemorySize, dsmem);

    // K1: all builds + transposes fused (independent work, co-running)
    prep_k<<<6400, 256>>>(segW1, maskS1, segW2, maskS2,
                          W1, maskW1, W2, maskW2, ctx, x);
    // FF layer 1 (needs xT, ellF1)
    fspmm<<<HID, 256>>>(xT, ellF1, cntF1, b1, yT);
    // K2: both layers' dendrite gates fused (need only ctxT)
    dspmm_gate2<<<256, 1024, dsmem>>>(ctxT);
    // layer 1 k-winners (applies gate 1), writes hT
    kwinners_k<<<BDIM, 256>>>(yT, gT1, hT, h2, 0);
    // FF layer 2
    fspmm<<<HID, 256>>>(hT, ellF2, cntF2, b2, yT);
    // layer 2 k-winners (applies gate 2), writes h2 row-major
    kwinners_k<<<BDIM, 256>>>(yT, gT2, hT, h2, 1);
    // EiDense head
    head_kernel<<<BDIM / 4, 256>>>(h2, Wex, Wix, Wei, bo, out);
}